// round 6
// baseline (speedup 1.0000x reference)
#include <cuda_runtime.h>
#include <cuda_bf16.h>
#include <math.h>
#include <stdint.h>

// Problem constants
#define SEQ    2048
#define DIN    4096
#define DOUT   4096
#define NH     32
#define NKV    8
#define HD     128
#define GROUP  4

// Scratch buffers
__device__ float g_Q[SEQ * DOUT];
__device__ float g_K[SEQ * (NKV * HD)];
__device__ float g_V[SEQ * (NKV * HD)];
__device__ float g_ctx[SEQ * DOUT];

__device__ __forceinline__ float f2tf32(float x) {
    float r;
    asm("cvt.rna.tf32.f32 %0, %1;" : "=f"(r) : "f"(x));
    return r;
}

__device__ __forceinline__ uint32_t cvt_u(uint32_t u) {
    float f = __uint_as_float(u);
    asm("cvt.rna.tf32.f32 %0, %1;" : "=f"(f) : "f"(f));
    return __float_as_uint(f);
}

__device__ __forceinline__ void mma_tf32(float* c, const uint32_t* a, const uint32_t* b) {
    asm volatile(
        "mma.sync.aligned.m16n8k8.row.col.f32.tf32.tf32.f32 "
        "{%0,%1,%2,%3}, {%4,%5,%6,%7}, {%8,%9}, {%0,%1,%2,%3};"
        : "+f"(c[0]), "+f"(c[1]), "+f"(c[2]), "+f"(c[3])
        : "r"(a[0]), "r"(a[1]), "r"(a[2]), "r"(a[3]), "r"(b[0]), "r"(b[1]));
}

__device__ __forceinline__ uint32_t smem_u32(const void* p) {
    uint32_t a;
    asm("{ .reg .u64 t; cvta.to.shared.u64 t, %1; cvt.u32.u64 %0, t; }"
        : "=r"(a) : "l"(p));
    return a;
}

__device__ __forceinline__ void cp16(uint32_t dst, const float* src) {
    asm volatile("cp.async.cg.shared.global [%0], [%1], 16;"
                 :: "r"(dst), "l"(src) : "memory");
}
#define CP_COMMIT() asm volatile("cp.async.commit_group;" ::: "memory")
#define CP_WAIT(n)  asm volatile("cp.async.wait_group %0;" :: "n"(n) : "memory")

// ===========================================================================
// cp.async tf32 GEMM core (unchanged from Round 5 — validated)
// ===========================================================================
#define GS 3
#define STAGE_BYTES 32768
#define GEMM_SMEM (GS * STAGE_BYTES)

__device__ __forceinline__ void gemm_core(
    const float* __restrict__ A, const float* __restrict__ B,
    float* __restrict__ C, int K, int ldc, int bm)
{
    extern __shared__ char sbuf[];
    const uint32_t sbase = smem_u32(sbuf);
    const int tid  = threadIdx.x;
    const int lane = tid & 31;
    const int warp = tid >> 5;
    const int gID  = lane >> 2;
    const int tig  = lane & 3;
    const int wm   = (warp & 1) * 64;
    const int wn   = (warp >> 1) * 64;

    const int fr = tid >> 3;
    const int fc = tid & 7;

    float acc[4][8][4];
#pragma unroll
    for (int mi = 0; mi < 4; mi++)
#pragma unroll
        for (int ni = 0; ni < 8; ni++)
#pragma unroll
            for (int j = 0; j < 4; j++) acc[mi][ni][j] = 0.f;

    const int nK = K >> 5;

    auto fill = [&](int st, int kt) {
        const uint32_t dA = sbase + st * STAGE_BYTES;
        const uint32_t dB = dA + 16384;
        const float* gA = A + (size_t)bm * K + kt * 32;
        const float* gB = B + (size_t)kt * 32;
#pragma unroll
        for (int i = 0; i < 8; i++) {
            const int r = fr + i * 16;
            const uint32_t sw = (uint32_t)(r * 128 + ((fc ^ (r & 7)) * 16));
            cp16(dA + sw, gA + (size_t)r * K + fc * 4);
            cp16(dB + sw, gB + (size_t)r * K + fc * 4);
        }
    };

#pragma unroll
    for (int s = 0; s < GS - 1; s++) {
        if (s < nK) fill(s, s);
        CP_COMMIT();
    }

    for (int kt = 0; kt < nK; kt++) {
        const int nxt = kt + GS - 1;
        if (nxt < nK) fill(nxt % GS, nxt);
        CP_COMMIT();
        CP_WAIT(2);
        __syncthreads();

        const uint32_t* Sa = (const uint32_t*)(sbuf + (kt % GS) * STAGE_BYTES);
        const uint32_t* Sb = Sa + 4096;

#pragma unroll
        for (int kk = 0; kk < 4; kk++) {
            const int K4 = kk * 2;
            const int x0 = ((K4 ^ gID) * 4 + tig);
            const int x1 = (((K4 + 1) ^ gID) * 4 + tig);

            uint32_t af[4][4], bf[8][2];
#pragma unroll
            for (int mi = 0; mi < 4; mi++) {
                const int r = wm + mi * 16 + gID;
                af[mi][0] = cvt_u(Sa[r * 32 + x0]);
                af[mi][1] = cvt_u(Sa[(r + 8) * 32 + x0]);
                af[mi][2] = cvt_u(Sa[r * 32 + x1]);
                af[mi][3] = cvt_u(Sa[(r + 8) * 32 + x1]);
            }
#pragma unroll
            for (int ni = 0; ni < 8; ni++) {
                const int n = wn + ni * 8 + gID;
                bf[ni][0] = cvt_u(Sb[n * 32 + x0]);
                bf[ni][1] = cvt_u(Sb[n * 32 + x1]);
            }
#pragma unroll
            for (int mi = 0; mi < 4; mi++)
#pragma unroll
                for (int ni = 0; ni < 8; ni++)
                    mma_tf32(acc[mi][ni], af[mi], bf[ni]);
        }
        __syncthreads();
    }

#pragma unroll
    for (int mi = 0; mi < 4; mi++) {
        const int r0 = bm + wm + mi * 16 + gID;
#pragma unroll
        for (int ni = 0; ni < 8; ni++) {
            const int c0 = wn + ni * 8 + tig * 2;
            const float* c = acc[mi][ni];
            *(float2*)(C + (size_t)r0 * ldc + c0)       = make_float2(c[0], c[1]);
            *(float2*)(C + (size_t)(r0 + 8) * ldc + c0) = make_float2(c[2], c[3]);
        }
    }
}

__global__ __launch_bounds__(128, 2) void gemm_qkv(
    const float* __restrict__ x,
    const float* __restrict__ Wq, const float* __restrict__ Wk,
    const float* __restrict__ Wv,
    float* __restrict__ Q, float* __restrict__ Ko, float* __restrict__ Vo)
{
    const int bn = blockIdx.x;
    const int bm = blockIdx.y * 128;
    const float* B;
    float* C;
    int ldc, coff;
    if (bn < 32)      { B = Wq; C = Q;  ldc = DOUT; coff = bn * 128; }
    else if (bn < 40) { B = Wk; C = Ko; ldc = NKV * HD; coff = (bn - 32) * 128; }
    else              { B = Wv; C = Vo; ldc = NKV * HD; coff = (bn - 40) * 128; }
    gemm_core(x, B + (size_t)coff * DIN, C + coff, DIN, ldc, bm);
}

__global__ __launch_bounds__(128, 2) void gemm_nt(
    const float* __restrict__ A, const float* __restrict__ B,
    float* __restrict__ C, int K, int N)
{
    const int coff = blockIdx.x * 128;
    gemm_core(A, B + (size_t)coff * K, C + coff, K, N, blockIdx.y * 128);
}

// ---------------------------------------------------------------------------
// RoPE (in place) on a [SEQ, H*128] row-major tensor.
// ---------------------------------------------------------------------------
__global__ __launch_bounds__(256) void rope_kernel(
    float* __restrict__ T, const float* __restrict__ cosT,
    const float* __restrict__ sinT, int H)
{
    int idx = blockIdx.x * blockDim.x + threadIdx.x;
    int total = SEQ * H * 64;
    if (idx >= total) return;
    int d = idx & 63;
    int h = (idx >> 6) % H;
    int s = idx / (64 * H);

    float* row = T + (size_t)s * (H * HD) + h * HD;
    float x1 = row[d];
    float x2 = row[d + 64];
    float c1 = cosT[s * HD + d],      s1 = sinT[s * HD + d];
    float c2 = cosT[s * HD + d + 64], s2 = sinT[s * HD + d + 64];
    row[d]      = fmaf(x1, c1, -x2 * s1);
    row[d + 64] = fmaf(x2, c2,  x1 * s2);
}

// ---------------------------------------------------------------------------
// Tensor-core flash attention, tf32 mma. Round 6: Ps smem buffer replaced by
// intra-quad shuffles (C-frag -> A-frag relayout of P), smem 117KB -> 100KB
// so 2 CTAs/SM.
// ---------------------------------------------------------------------------
#define BQ   64
#define BKV  64
#define QKS  132
#define VS_  136

__global__ __launch_bounds__(128, 2) void attn_mma(
    const float* __restrict__ Q, const float* __restrict__ K,
    const float* __restrict__ V, float* __restrict__ ctx)
{
    const int qb  = gridDim.x - 1 - blockIdx.x;
    const int h   = blockIdx.y;
    const int hk  = h >> 2;
    const int tid = threadIdx.x;
    const int lane = tid & 31;
    const int warp = tid >> 5;
    const int gID  = lane >> 2;
    const int tig  = lane & 3;
    const int wrow = warp * 16;

    extern __shared__ float sm[];
    float* Qs = sm;                  // [64][132]
    float* Ks = Qs + BQ * QKS;       // [64][132]
    float* Vs = Ks + BKV * QKS;      // [64][136]

    const float scale = 0.08838834764831845f;

    {
        int r = tid >> 1;
        int cb = (tid & 1) * 64;
        const float* src = Q + (size_t)(qb * BQ + r) * DOUT + h * HD + cb;
        float* dst = Qs + r * QKS + cb;
#pragma unroll
        for (int c = 0; c < 64; c += 4) {
            float4 q4 = *(const float4*)(src + c);
            dst[c + 0] = f2tf32(q4.x * scale);
            dst[c + 1] = f2tf32(q4.y * scale);
            dst[c + 2] = f2tf32(q4.z * scale);
            dst[c + 3] = f2tf32(q4.w * scale);
        }
    }

    float mrow[2] = {-1e30f, -1e30f};
    float lrow[2] = {0.f, 0.f};
    float accO[16][4];
#pragma unroll
    for (int i = 0; i < 16; i++)
#pragma unroll
        for (int j = 0; j < 4; j++) accO[i][j] = 0.f;

    // srclanes for P C-frag -> A-frag shuffles (constant per thread)
    const int src0 = (lane & ~3) | (tig >> 1);
    const int src1 = src0 + 2;
    const bool oddt = (tig & 1);

    for (int kb = 0; kb <= qb; kb++) {
        __syncthreads();

        {
            int r = tid >> 1;
            int cb = (tid & 1) * 64;
            const float* ksrc = K + (size_t)(kb * BKV + r) * (NKV * HD) + hk * HD + cb;
            const float* vsrc = V + (size_t)(kb * BKV + r) * (NKV * HD) + hk * HD + cb;
            float* kdst = Ks + r * QKS + cb;
            float* vdst = Vs + r * VS_ + cb;
#pragma unroll
            for (int c = 0; c < 64; c += 4) {
                float4 k4 = *(const float4*)(ksrc + c);
                kdst[c + 0] = f2tf32(k4.x); kdst[c + 1] = f2tf32(k4.y);
                kdst[c + 2] = f2tf32(k4.z); kdst[c + 3] = f2tf32(k4.w);
                float4 v4 = *(const float4*)(vsrc + c);
                vdst[c + 0] = f2tf32(v4.x); vdst[c + 1] = f2tf32(v4.y);
                vdst[c + 2] = f2tf32(v4.z); vdst[c + 3] = f2tf32(v4.w);
            }
        }
        __syncthreads();

        // ---- S = Q @ K^T : warp computes 16x64 ----
        float accS[8][4];
#pragma unroll
        for (int i = 0; i < 8; i++)
#pragma unroll
            for (int j = 0; j < 4; j++) accS[i][j] = 0.f;

        const uint32_t* Qu = (const uint32_t*)Qs;
        const uint32_t* Ku = (const uint32_t*)Ks;
#pragma unroll
        for (int ks = 0; ks < 16; ks++) {
            const int k = ks * 8;
            uint32_t a[4];
            a[0] = Qu[(wrow + gID)     * QKS + k + tig];
            a[1] = Qu[(wrow + gID + 8) * QKS + k + tig];
            a[2] = Qu[(wrow + gID)     * QKS + k + tig + 4];
            a[3] = Qu[(wrow + gID + 8) * QKS + k + tig + 4];
#pragma unroll
            for (int nt = 0; nt < 8; nt++) {
                uint32_t b[2];
                b[0] = Ku[(nt * 8 + gID) * QKS + k + tig];
                b[1] = Ku[(nt * 8 + gID) * QKS + k + tig + 4];
                mma_tf32(accS[nt], a, b);
            }
        }

        if (kb == qb) {
            int r0 = wrow + gID;
            int r1 = r0 + 8;
#pragma unroll
            for (int nt = 0; nt < 8; nt++) {
                int c0 = nt * 8 + 2 * tig;
                if (c0 > r0)     accS[nt][0] = -1e30f;
                if (c0 + 1 > r0) accS[nt][1] = -1e30f;
                if (c0 > r1)     accS[nt][2] = -1e30f;
                if (c0 + 1 > r1) accS[nt][3] = -1e30f;
            }
        }

        // ---- online softmax (register) ----
        float mx0 = -1e30f, mx1 = -1e30f;
#pragma unroll
        for (int nt = 0; nt < 8; nt++) {
            mx0 = fmaxf(mx0, fmaxf(accS[nt][0], accS[nt][1]));
            mx1 = fmaxf(mx1, fmaxf(accS[nt][2], accS[nt][3]));
        }
        mx0 = fmaxf(mx0, __shfl_xor_sync(0xffffffffu, mx0, 1));
        mx0 = fmaxf(mx0, __shfl_xor_sync(0xffffffffu, mx0, 2));
        mx1 = fmaxf(mx1, __shfl_xor_sync(0xffffffffu, mx1, 1));
        mx1 = fmaxf(mx1, __shfl_xor_sync(0xffffffffu, mx1, 2));

        float mn0 = fmaxf(mrow[0], mx0);
        float mn1 = fmaxf(mrow[1], mx1);
        float al0 = __expf(mrow[0] - mn0);
        float al1 = __expf(mrow[1] - mn1);
        mrow[0] = mn0; mrow[1] = mn1;

        float ls0 = 0.f, ls1 = 0.f;
#pragma unroll
        for (int nt = 0; nt < 8; nt++) {
            float p0 = __expf(accS[nt][0] - mn0);
            float p1 = __expf(accS[nt][1] - mn0);
            float p2 = __expf(accS[nt][2] - mn1);
            float p3 = __expf(accS[nt][3] - mn1);
            ls0 += p0 + p1;
            ls1 += p2 + p3;
            // store P back as tf32-rounded floats (C-frag layout, in regs)
            accS[nt][0] = f2tf32(p0);
            accS[nt][1] = f2tf32(p1);
            accS[nt][2] = f2tf32(p2);
            accS[nt][3] = f2tf32(p3);
        }
        ls0 += __shfl_xor_sync(0xffffffffu, ls0, 1);
        ls0 += __shfl_xor_sync(0xffffffffu, ls0, 2);
        ls1 += __shfl_xor_sync(0xffffffffu, ls1, 1);
        ls1 += __shfl_xor_sync(0xffffffffu, ls1, 2);
        lrow[0] = lrow[0] * al0 + ls0;
        lrow[1] = lrow[1] * al1 + ls1;

#pragma unroll
        for (int nt = 0; nt < 16; nt++) {
            accO[nt][0] *= al0; accO[nt][1] *= al0;
            accO[nt][2] *= al1; accO[nt][3] *= al1;
        }

        // ---- O += P @ V : P A-frags built via intra-quad shuffles ----
        const uint32_t* Vu = (const uint32_t*)Vs;
#pragma unroll
        for (int kt = 0; kt < 8; kt++) {
            const int k = kt * 8;
            // A-frag of P for this k-tile from accS[kt] (C-frag layout)
            uint32_t a[4];
            {
                uint32_t p0 = __float_as_uint(accS[kt][0]);
                uint32_t p1 = __float_as_uint(accS[kt][1]);
                uint32_t p2 = __float_as_uint(accS[kt][2]);
                uint32_t p3 = __float_as_uint(accS[kt][3]);
                uint32_t lo, hi;
                lo = __shfl_sync(0xffffffffu, p0, src0);
                hi = __shfl_sync(0xffffffffu, p1, src0);
                a[0] = oddt ? hi : lo;
                lo = __shfl_sync(0xffffffffu, p2, src0);
                hi = __shfl_sync(0xffffffffu, p3, src0);
                a[1] = oddt ? hi : lo;
                lo = __shfl_sync(0xffffffffu, p0, src1);
                hi = __shfl_sync(0xffffffffu, p1, src1);
                a[2] = oddt ? hi : lo;
                lo = __shfl_sync(0xffffffffu, p2, src1);
                hi = __shfl_sync(0xffffffffu, p3, src1);
                a[3] = oddt ? hi : lo;
            }
#pragma unroll
            for (int nt = 0; nt < 16; nt++) {
                uint32_t b[2];
                b[0] = Vu[(k + tig)     * VS_ + nt * 8 + gID];
                b[1] = Vu[(k + tig + 4) * VS_ + nt * 8 + gID];
                mma_tf32(accO[nt], a, b);
            }
        }
    }

    float li0 = 1.f / lrow[0];
    float li1 = 1.f / lrow[1];
    int r0 = qb * BQ + wrow + gID;
    int r1 = r0 + 8;
#pragma unroll
    for (int nt = 0; nt < 16; nt++) {
        int c = h * HD + nt * 8 + 2 * tig;
        *(float2*)(ctx + (size_t)r0 * DOUT + c) =
            make_float2(accO[nt][0] * li0, accO[nt][1] * li0);
        *(float2*)(ctx + (size_t)r1 * DOUT + c) =
            make_float2(accO[nt][2] * li1, accO[nt][3] * li1);
    }
}

// ---------------------------------------------------------------------------
// Launch
// ---------------------------------------------------------------------------
extern "C" void kernel_launch(void* const* d_in, const int* in_sizes, int n_in,
                              void* d_out, int out_size)
{
    const float* x    = (const float*)d_in[0];
    const float* cosT = (const float*)d_in[1];
    const float* sinT = (const float*)d_in[2];
    const float* Wq   = (const float*)d_in[3];
    const float* Wk   = (const float*)d_in[4];
    const float* Wv   = (const float*)d_in[5];
    const float* Wo   = (const float*)d_in[6];
    float* out = (float*)d_out;

    float *Qp, *Kp, *Vp, *Cp;
    cudaGetSymbolAddress((void**)&Qp, g_Q);
    cudaGetSymbolAddress((void**)&Kp, g_K);
    cudaGetSymbolAddress((void**)&Vp, g_V);
    cudaGetSymbolAddress((void**)&Cp, g_ctx);

    cudaFuncSetAttribute(gemm_qkv, cudaFuncAttributeMaxDynamicSharedMemorySize, GEMM_SMEM);
    cudaFuncSetAttribute(gemm_nt,  cudaFuncAttributeMaxDynamicSharedMemorySize, GEMM_SMEM);

    const int ATTN_SMEM = (BQ * QKS + BKV * QKS + BKV * VS_) * (int)sizeof(float);
    cudaFuncSetAttribute(attn_mma, cudaFuncAttributeMaxDynamicSharedMemorySize, ATTN_SMEM);

    // Fused QKV projection
    gemm_qkv<<<dim3(48, SEQ / 128), 128, GEMM_SMEM>>>(x, Wq, Wk, Wv, Qp, Kp, Vp);

    // RoPE on Q and K
    {
        int totQ = SEQ * NH * 64;
        rope_kernel<<<(totQ + 255) / 256, 256>>>(Qp, cosT, sinT, NH);
        int totK = SEQ * NKV * 64;
        rope_kernel<<<(totK + 255) / 256, 256>>>(Kp, cosT, sinT, NKV);
    }

    // Tensor-core flash attention
    attn_mma<<<dim3(SEQ / BQ, NH), 128, ATTN_SMEM>>>(Qp, Kp, Vp, Cp);

    // Output projection
    gemm_nt<<<dim3(DOUT / 128, SEQ / 128), 128, GEMM_SMEM>>>(Cp, Wo, out, DIN, DOUT);
}

// round 7
// speedup vs baseline: 1.1206x; 1.1206x over previous
#include <cuda_runtime.h>
#include <cuda_bf16.h>
#include <math.h>
#include <stdint.h>

// Problem constants
#define SEQ    2048
#define DIN    4096
#define DOUT   4096
#define NH     32
#define NKV    8
#define HD     128
#define GROUP  4

// Scratch buffers
__device__ float g_Q[SEQ * DOUT];
__device__ float g_K[SEQ * (NKV * HD)];
__device__ float g_V[SEQ * (NKV * HD)];
__device__ float g_ctx[SEQ * DOUT];

__device__ __forceinline__ float f2tf32(float x) {
    float r;
    asm("cvt.rna.tf32.f32 %0, %1;" : "=f"(r) : "f"(x));
    return r;
}

__device__ __forceinline__ uint32_t cvt_u(uint32_t u) {
    float f = __uint_as_float(u);
    asm("cvt.rna.tf32.f32 %0, %1;" : "=f"(f) : "f"(f));
    return __float_as_uint(f);
}

__device__ __forceinline__ void mma_tf32(float* c, const uint32_t* a, const uint32_t* b) {
    asm volatile(
        "mma.sync.aligned.m16n8k8.row.col.f32.tf32.tf32.f32 "
        "{%0,%1,%2,%3}, {%4,%5,%6,%7}, {%8,%9}, {%0,%1,%2,%3};"
        : "+f"(c[0]), "+f"(c[1]), "+f"(c[2]), "+f"(c[3])
        : "r"(a[0]), "r"(a[1]), "r"(a[2]), "r"(a[3]), "r"(b[0]), "r"(b[1]));
}

__device__ __forceinline__ uint32_t smem_u32(const void* p) {
    uint32_t a;
    asm("{ .reg .u64 t; cvta.to.shared.u64 t, %1; cvt.u32.u64 %0, t; }"
        : "=r"(a) : "l"(p));
    return a;
}

__device__ __forceinline__ void cp16(uint32_t dst, const float* src) {
    asm volatile("cp.async.cg.shared.global [%0], [%1], 16;"
                 :: "r"(dst), "l"(src) : "memory");
}
#define CP_COMMIT() asm volatile("cp.async.commit_group;" ::: "memory")
#define CP_WAIT(n)  asm volatile("cp.async.wait_group %0;" :: "n"(n) : "memory")

// ===========================================================================
// cp.async tf32 GEMM core (unchanged from Round 5 — validated)
// ===========================================================================
#define GS 3
#define STAGE_BYTES 32768
#define GEMM_SMEM (GS * STAGE_BYTES)

__device__ __forceinline__ void gemm_core(
    const float* __restrict__ A, const float* __restrict__ B,
    float* __restrict__ C, int K, int ldc, int bm)
{
    extern __shared__ char sbuf[];
    const uint32_t sbase = smem_u32(sbuf);
    const int tid  = threadIdx.x;
    const int lane = tid & 31;
    const int warp = tid >> 5;
    const int gID  = lane >> 2;
    const int tig  = lane & 3;
    const int wm   = (warp & 1) * 64;
    const int wn   = (warp >> 1) * 64;

    const int fr = tid >> 3;
    const int fc = tid & 7;

    float acc[4][8][4];
#pragma unroll
    for (int mi = 0; mi < 4; mi++)
#pragma unroll
        for (int ni = 0; ni < 8; ni++)
#pragma unroll
            for (int j = 0; j < 4; j++) acc[mi][ni][j] = 0.f;

    const int nK = K >> 5;

    auto fill = [&](int st, int kt) {
        const uint32_t dA = sbase + st * STAGE_BYTES;
        const uint32_t dB = dA + 16384;
        const float* gA = A + (size_t)bm * K + kt * 32;
        const float* gB = B + (size_t)kt * 32;
#pragma unroll
        for (int i = 0; i < 8; i++) {
            const int r = fr + i * 16;
            const uint32_t sw = (uint32_t)(r * 128 + ((fc ^ (r & 7)) * 16));
            cp16(dA + sw, gA + (size_t)r * K + fc * 4);
            cp16(dB + sw, gB + (size_t)r * K + fc * 4);
        }
    };

#pragma unroll
    for (int s = 0; s < GS - 1; s++) {
        if (s < nK) fill(s, s);
        CP_COMMIT();
    }

    for (int kt = 0; kt < nK; kt++) {
        const int nxt = kt + GS - 1;
        if (nxt < nK) fill(nxt % GS, nxt);
        CP_COMMIT();
        CP_WAIT(2);
        __syncthreads();

        const uint32_t* Sa = (const uint32_t*)(sbuf + (kt % GS) * STAGE_BYTES);
        const uint32_t* Sb = Sa + 4096;

#pragma unroll
        for (int kk = 0; kk < 4; kk++) {
            const int K4 = kk * 2;
            const int x0 = ((K4 ^ gID) * 4 + tig);
            const int x1 = (((K4 + 1) ^ gID) * 4 + tig);

            uint32_t af[4][4], bf[8][2];
#pragma unroll
            for (int mi = 0; mi < 4; mi++) {
                const int r = wm + mi * 16 + gID;
                af[mi][0] = cvt_u(Sa[r * 32 + x0]);
                af[mi][1] = cvt_u(Sa[(r + 8) * 32 + x0]);
                af[mi][2] = cvt_u(Sa[r * 32 + x1]);
                af[mi][3] = cvt_u(Sa[(r + 8) * 32 + x1]);
            }
#pragma unroll
            for (int ni = 0; ni < 8; ni++) {
                const int n = wn + ni * 8 + gID;
                bf[ni][0] = cvt_u(Sb[n * 32 + x0]);
                bf[ni][1] = cvt_u(Sb[n * 32 + x1]);
            }
#pragma unroll
            for (int mi = 0; mi < 4; mi++)
#pragma unroll
                for (int ni = 0; ni < 8; ni++)
                    mma_tf32(acc[mi][ni], af[mi], bf[ni]);
        }
        __syncthreads();
    }

#pragma unroll
    for (int mi = 0; mi < 4; mi++) {
        const int r0 = bm + wm + mi * 16 + gID;
#pragma unroll
        for (int ni = 0; ni < 8; ni++) {
            const int c0 = wn + ni * 8 + tig * 2;
            const float* c = acc[mi][ni];
            *(float2*)(C + (size_t)r0 * ldc + c0)       = make_float2(c[0], c[1]);
            *(float2*)(C + (size_t)(r0 + 8) * ldc + c0) = make_float2(c[2], c[3]);
        }
    }
}

__global__ __launch_bounds__(128, 2) void gemm_qkv(
    const float* __restrict__ x,
    const float* __restrict__ Wq, const float* __restrict__ Wk,
    const float* __restrict__ Wv,
    float* __restrict__ Q, float* __restrict__ Ko, float* __restrict__ Vo)
{
    const int bn = blockIdx.x;
    const int bm = blockIdx.y * 128;
    const float* B;
    float* C;
    int ldc, coff;
    if (bn < 32)      { B = Wq; C = Q;  ldc = DOUT; coff = bn * 128; }
    else if (bn < 40) { B = Wk; C = Ko; ldc = NKV * HD; coff = (bn - 32) * 128; }
    else              { B = Wv; C = Vo; ldc = NKV * HD; coff = (bn - 40) * 128; }
    gemm_core(x, B + (size_t)coff * DIN, C + coff, DIN, ldc, bm);
}

__global__ __launch_bounds__(128, 2) void gemm_nt(
    const float* __restrict__ A, const float* __restrict__ B,
    float* __restrict__ C, int K, int N)
{
    const int coff = blockIdx.x * 128;
    gemm_core(A, B + (size_t)coff * K, C + coff, K, N, blockIdx.y * 128);
}

// ---------------------------------------------------------------------------
// RoPE (in place) on a [SEQ, H*128] row-major tensor.
// ---------------------------------------------------------------------------
__global__ __launch_bounds__(256) void rope_kernel(
    float* __restrict__ T, const float* __restrict__ cosT,
    const float* __restrict__ sinT, int H)
{
    int idx = blockIdx.x * blockDim.x + threadIdx.x;
    int total = SEQ * H * 64;
    if (idx >= total) return;
    int d = idx & 63;
    int h = (idx >> 6) % H;
    int s = idx / (64 * H);

    float* row = T + (size_t)s * (H * HD) + h * HD;
    float x1 = row[d];
    float x2 = row[d + 64];
    float c1 = cosT[s * HD + d],      s1 = sinT[s * HD + d];
    float c2 = cosT[s * HD + d + 64], s2 = sinT[s * HD + d + 64];
    row[d]      = fmaf(x1, c1, -x2 * s1);
    row[d + 64] = fmaf(x2, c2,  x1 * s2);
}

// ---------------------------------------------------------------------------
// Tensor-core flash attention, tf32 mma. Round 7: BQ=128, warp owns 32 q-rows
// (2 m-tiles) so every K/V B-fragment feeds 2 MMAs. P staged via smem (R5
// scheme — shuffles reverted).
// ---------------------------------------------------------------------------
#define BQ   128
#define BKV  64
#define QKS  132
#define VS_  136
#define PS_  68

__global__ __launch_bounds__(128, 1) void attn_mma(
    const float* __restrict__ Q, const float* __restrict__ K,
    const float* __restrict__ V, float* __restrict__ ctx)
{
    const int qb  = gridDim.x - 1 - blockIdx.x;   // long rows first
    const int h   = blockIdx.y;
    const int hk  = h >> 2;
    const int tid = threadIdx.x;
    const int lane = tid & 31;
    const int warp = tid >> 5;
    const int gID  = lane >> 2;
    const int tig  = lane & 3;
    const int wrow = warp * 32;     // warp's q-row offset (32 rows)

    extern __shared__ float sm[];
    float* Qs = sm;                  // [128][132]
    float* Ks = Qs + BQ * QKS;       // [64][132]
    float* Vs = Ks + BKV * QKS;      // [64][136]
    float* Ps = Vs + BKV * VS_;      // [128][68]

    const float scale = 0.08838834764831845f;  // 1/sqrt(128)

    // Load Q tile (scaled + tf32): thread -> one row of 128
    {
        const int r = tid;
        const float* src = Q + (size_t)(qb * BQ + r) * DOUT + h * HD;
        float* dst = Qs + r * QKS;
#pragma unroll
        for (int c = 0; c < 128; c += 4) {
            float4 q4 = *(const float4*)(src + c);
            dst[c + 0] = f2tf32(q4.x * scale);
            dst[c + 1] = f2tf32(q4.y * scale);
            dst[c + 2] = f2tf32(q4.z * scale);
            dst[c + 3] = f2tf32(q4.w * scale);
        }
    }

    // state per m-tile (mi), per row-half (gID row / gID+8 row)
    float mrow[2][2] = {{-1e30f, -1e30f}, {-1e30f, -1e30f}};
    float lrow[2][2] = {{0.f, 0.f}, {0.f, 0.f}};
    float accO[2][16][4];
#pragma unroll
    for (int mi = 0; mi < 2; mi++)
#pragma unroll
        for (int i = 0; i < 16; i++)
#pragma unroll
            for (int j = 0; j < 4; j++) accO[mi][i][j] = 0.f;

    const int nkb = 2 * qb + 2;
    for (int kb = 0; kb < nkb; kb++) {
        __syncthreads();   // prev iter done reading Ks/Vs

        // Load K,V tiles (tf32): 64x128 each, 128 threads
        {
            int r = tid >> 1;
            int cb = (tid & 1) * 64;
            const float* ksrc = K + (size_t)(kb * BKV + r) * (NKV * HD) + hk * HD + cb;
            const float* vsrc = V + (size_t)(kb * BKV + r) * (NKV * HD) + hk * HD + cb;
            float* kdst = Ks + r * QKS + cb;
            float* vdst = Vs + r * VS_ + cb;
#pragma unroll
            for (int c = 0; c < 64; c += 4) {
                float4 k4 = *(const float4*)(ksrc + c);
                kdst[c + 0] = f2tf32(k4.x); kdst[c + 1] = f2tf32(k4.y);
                kdst[c + 2] = f2tf32(k4.z); kdst[c + 3] = f2tf32(k4.w);
                float4 v4 = *(const float4*)(vsrc + c);
                vdst[c + 0] = f2tf32(v4.x); vdst[c + 1] = f2tf32(v4.y);
                vdst[c + 2] = f2tf32(v4.z); vdst[c + 3] = f2tf32(v4.w);
            }
        }
        __syncthreads();

        // ---- S = Q @ K^T : warp computes 32x64 (2 m-tiles) ----
        float accS[2][8][4];
#pragma unroll
        for (int mi = 0; mi < 2; mi++)
#pragma unroll
            for (int i = 0; i < 8; i++)
#pragma unroll
                for (int j = 0; j < 4; j++) accS[mi][i][j] = 0.f;

        const uint32_t* Qu = (const uint32_t*)Qs;
        const uint32_t* Ku = (const uint32_t*)Ks;
#pragma unroll
        for (int ks = 0; ks < 16; ks++) {
            const int k = ks * 8;
            uint32_t a[2][4];
#pragma unroll
            for (int mi = 0; mi < 2; mi++) {
                const int r = wrow + mi * 16 + gID;
                a[mi][0] = Qu[r * QKS + k + tig];
                a[mi][1] = Qu[(r + 8) * QKS + k + tig];
                a[mi][2] = Qu[r * QKS + k + tig + 4];
                a[mi][3] = Qu[(r + 8) * QKS + k + tig + 4];
            }
#pragma unroll
            for (int nt = 0; nt < 8; nt++) {
                uint32_t b[2];
                b[0] = Ku[(nt * 8 + gID) * QKS + k + tig];
                b[1] = Ku[(nt * 8 + gID) * QKS + k + tig + 4];
                mma_tf32(accS[0][nt], a[0], b);
                mma_tf32(accS[1][nt], a[1], b);
            }
        }

        // ---- causal mask (only tiles that can cross the diagonal) ----
        if (kb >= 2 * qb) {
#pragma unroll
            for (int mi = 0; mi < 2; mi++) {
                const int q0 = qb * BQ + wrow + mi * 16 + gID;
                const int q1 = q0 + 8;
#pragma unroll
                for (int nt = 0; nt < 8; nt++) {
                    const int kg = kb * BKV + nt * 8 + 2 * tig;
                    if (kg > q0)     accS[mi][nt][0] = -1e30f;
                    if (kg + 1 > q0) accS[mi][nt][1] = -1e30f;
                    if (kg > q1)     accS[mi][nt][2] = -1e30f;
                    if (kg + 1 > q1) accS[mi][nt][3] = -1e30f;
                }
            }
        }

        // ---- online softmax + P store (per m-tile) ----
#pragma unroll
        for (int mi = 0; mi < 2; mi++) {
            float mx0 = -1e30f, mx1 = -1e30f;
#pragma unroll
            for (int nt = 0; nt < 8; nt++) {
                mx0 = fmaxf(mx0, fmaxf(accS[mi][nt][0], accS[mi][nt][1]));
                mx1 = fmaxf(mx1, fmaxf(accS[mi][nt][2], accS[mi][nt][3]));
            }
            mx0 = fmaxf(mx0, __shfl_xor_sync(0xffffffffu, mx0, 1));
            mx0 = fmaxf(mx0, __shfl_xor_sync(0xffffffffu, mx0, 2));
            mx1 = fmaxf(mx1, __shfl_xor_sync(0xffffffffu, mx1, 1));
            mx1 = fmaxf(mx1, __shfl_xor_sync(0xffffffffu, mx1, 2));

            float mn0 = fmaxf(mrow[mi][0], mx0);
            float mn1 = fmaxf(mrow[mi][1], mx1);
            float al0 = __expf(mrow[mi][0] - mn0);
            float al1 = __expf(mrow[mi][1] - mn1);
            mrow[mi][0] = mn0; mrow[mi][1] = mn1;

            float ls0 = 0.f, ls1 = 0.f;
            const int r0 = wrow + mi * 16 + gID;
#pragma unroll
            for (int nt = 0; nt < 8; nt++) {
                float p0 = __expf(accS[mi][nt][0] - mn0);
                float p1 = __expf(accS[mi][nt][1] - mn0);
                float p2 = __expf(accS[mi][nt][2] - mn1);
                float p3 = __expf(accS[mi][nt][3] - mn1);
                ls0 += p0 + p1;
                ls1 += p2 + p3;
                const int c = nt * 8 + 2 * tig;
                *(float2*)(Ps + r0 * PS_ + c)       = make_float2(f2tf32(p0), f2tf32(p1));
                *(float2*)(Ps + (r0 + 8) * PS_ + c) = make_float2(f2tf32(p2), f2tf32(p3));
            }
            ls0 += __shfl_xor_sync(0xffffffffu, ls0, 1);
            ls0 += __shfl_xor_sync(0xffffffffu, ls0, 2);
            ls1 += __shfl_xor_sync(0xffffffffu, ls1, 1);
            ls1 += __shfl_xor_sync(0xffffffffu, ls1, 2);
            lrow[mi][0] = lrow[mi][0] * al0 + ls0;
            lrow[mi][1] = lrow[mi][1] * al1 + ls1;

#pragma unroll
            for (int nt = 0; nt < 16; nt++) {
                accO[mi][nt][0] *= al0; accO[mi][nt][1] *= al0;
                accO[mi][nt][2] *= al1; accO[mi][nt][3] *= al1;
            }
        }
        __syncwarp();   // Ps rows are warp-private

        // ---- O += P @ V : warp computes 32x128 ----
        const uint32_t* Pu = (const uint32_t*)Ps;
        const uint32_t* Vu = (const uint32_t*)Vs;
#pragma unroll
        for (int kt = 0; kt < 8; kt++) {
            const int k = kt * 8;
            uint32_t a[2][4];
#pragma unroll
            for (int mi = 0; mi < 2; mi++) {
                const int r = wrow + mi * 16 + gID;
                a[mi][0] = Pu[r * PS_ + k + tig];
                a[mi][1] = Pu[(r + 8) * PS_ + k + tig];
                a[mi][2] = Pu[r * PS_ + k + tig + 4];
                a[mi][3] = Pu[(r + 8) * PS_ + k + tig + 4];
            }
#pragma unroll
            for (int nt = 0; nt < 16; nt++) {
                uint32_t b[2];
                b[0] = Vu[(k + tig)     * VS_ + nt * 8 + gID];
                b[1] = Vu[(k + tig + 4) * VS_ + nt * 8 + gID];
                mma_tf32(accO[0][nt], a[0], b);
                mma_tf32(accO[1][nt], a[1], b);
            }
        }
    }

    // epilogue: normalize and store
#pragma unroll
    for (int mi = 0; mi < 2; mi++) {
        const float li0 = 1.f / lrow[mi][0];
        const float li1 = 1.f / lrow[mi][1];
        const int r0 = qb * BQ + wrow + mi * 16 + gID;
        const int r1 = r0 + 8;
#pragma unroll
        for (int nt = 0; nt < 16; nt++) {
            const int c = h * HD + nt * 8 + 2 * tig;
            *(float2*)(ctx + (size_t)r0 * DOUT + c) =
                make_float2(accO[mi][nt][0] * li0, accO[mi][nt][1] * li0);
            *(float2*)(ctx + (size_t)r1 * DOUT + c) =
                make_float2(accO[mi][nt][2] * li1, accO[mi][nt][3] * li1);
        }
    }
}

// ---------------------------------------------------------------------------
// Launch
// ---------------------------------------------------------------------------
extern "C" void kernel_launch(void* const* d_in, const int* in_sizes, int n_in,
                              void* d_out, int out_size)
{
    const float* x    = (const float*)d_in[0];
    const float* cosT = (const float*)d_in[1];
    const float* sinT = (const float*)d_in[2];
    const float* Wq   = (const float*)d_in[3];
    const float* Wk   = (const float*)d_in[4];
    const float* Wv   = (const float*)d_in[5];
    const float* Wo   = (const float*)d_in[6];
    float* out = (float*)d_out;

    float *Qp, *Kp, *Vp, *Cp;
    cudaGetSymbolAddress((void**)&Qp, g_Q);
    cudaGetSymbolAddress((void**)&Kp, g_K);
    cudaGetSymbolAddress((void**)&Vp, g_V);
    cudaGetSymbolAddress((void**)&Cp, g_ctx);

    cudaFuncSetAttribute(gemm_qkv, cudaFuncAttributeMaxDynamicSharedMemorySize, GEMM_SMEM);
    cudaFuncSetAttribute(gemm_nt,  cudaFuncAttributeMaxDynamicSharedMemorySize, GEMM_SMEM);

    const int ATTN_SMEM = (BQ * QKS + BKV * QKS + BKV * VS_ + BQ * PS_) * (int)sizeof(float);
    cudaFuncSetAttribute(attn_mma, cudaFuncAttributeMaxDynamicSharedMemorySize, ATTN_SMEM);

    // Fused QKV projection
    gemm_qkv<<<dim3(48, SEQ / 128), 128, GEMM_SMEM>>>(x, Wq, Wk, Wv, Qp, Kp, Vp);

    // RoPE on Q and K
    {
        int totQ = SEQ * NH * 64;
        rope_kernel<<<(totQ + 255) / 256, 256>>>(Qp, cosT, sinT, NH);
        int totK = SEQ * NKV * 64;
        rope_kernel<<<(totK + 255) / 256, 256>>>(Kp, cosT, sinT, NKV);
    }

    // Tensor-core flash attention (BQ=128)
    attn_mma<<<dim3(SEQ / BQ, NH), 128, ATTN_SMEM>>>(Qp, Kp, Vp, Cp);

    // Output projection
    gemm_nt<<<dim3(DOUT / 128, SEQ / 128), 128, GEMM_SMEM>>>(Cp, Wo, out, DIN, DOUT);
}